// round 8
// baseline (speedup 1.0000x reference)
#include <cuda_runtime.h>
#include <math.h>

// Problem dims
#define B_   256
#define O_   128
#define H_   1024
#define Hh_  512
#define I_   2048
#define DF_  1536

// Scratch (static device memory: allocation-free, graph-capturable)
__device__ int   g_mask_u8;                  // S0 out: 1 if mask is byte-packed bool
__device__ float g_hWe[B_ * Hh_];            // S1 out: h@We^T + b_e   (256x512)
__device__ float g_scores[B_ * O_];          // S2 out: attention logits (256x128)
__device__ float g_phi[B_ * Hh_];            // S3 out: attended x_j    (256x512)
__device__ float g_part[4 * 4 * B_ * H_];    // S4 out: [ksplit][gate][b][n] partials

struct GatePtrs { const float* W[4]; const float* U[4]; const float* V[4]; };
struct BiasPtrs { const float* b[4]; };

// ---------------------------------------------------------------------------
// S0: detect mask encoding. Reads the first B*O/4 32-bit words (= 32 KB,
//     in-bounds whether the buffer is uint8 (32 KB), int32 or f32 (128 KB)).
//     int32 bool -> words in {0,1}; f32 bool -> {0, 0x3F800000};
//     byte-packed bool -> words like 0x01010101 appear w.p. ~1.
//     Deterministic: same input -> same flag every launch.
// ---------------------------------------------------------------------------
__global__ void s0_detect_kernel(const unsigned int* __restrict__ mw) {
    __shared__ int bad;
    if (threadIdx.x == 0) bad = 0;
    __syncthreads();
    int mybad = 0;
    for (int i = threadIdx.x; i < (B_ * O_) / 4; i += blockDim.x) {
        unsigned int v = mw[i];
        if (v != 0u && v != 1u && v != 0x3F800000u) mybad = 1;
    }
    if (mybad) bad = 1;           // benign race: only ever writes 1
    __syncthreads();
    if (threadIdx.x == 0) g_mask_u8 = bad;
}

// ---------------------------------------------------------------------------
// S1: g_hWe[b][n] = b_e[n] + sum_j h[b][j] * W_e[n][j]
//     M=256, N=512, K=1024. BM=BN=64, BK=16, 256 thr, 4x4 microtile.
// ---------------------------------------------------------------------------
__global__ __launch_bounds__(256) void s1_kernel(const float* __restrict__ h,
                                                 const float* __restrict__ We,
                                                 const float* __restrict__ be) {
    __shared__ __align__(16) float As[16][68];
    __shared__ __align__(16) float Bs[16][68];
    const int tid = threadIdx.x;
    const int tx = tid & 15, ty = tid >> 4;
    const int m0 = blockIdx.x * 64, n0 = blockIdx.y * 64;
    const int lrow = tid >> 2;
    const int lc4  = (tid & 3) * 4;

    float acc[4][4] = {};
    for (int k0 = 0; k0 < H_; k0 += 16) {
        float4 av = *(const float4*)(h  + (size_t)(m0 + lrow) * H_ + k0 + lc4);
        float4 bv = *(const float4*)(We + (size_t)(n0 + lrow) * H_ + k0 + lc4);
        __syncthreads();
        As[lc4 + 0][lrow] = av.x; As[lc4 + 1][lrow] = av.y;
        As[lc4 + 2][lrow] = av.z; As[lc4 + 3][lrow] = av.w;
        Bs[lc4 + 0][lrow] = bv.x; Bs[lc4 + 1][lrow] = bv.y;
        Bs[lc4 + 2][lrow] = bv.z; Bs[lc4 + 3][lrow] = bv.w;
        __syncthreads();
#pragma unroll
        for (int k = 0; k < 16; k++) {
            float a[4], bb[4];
            *(float4*)a  = *(const float4*)&As[k][ty * 4];
            *(float4*)bb = *(const float4*)&Bs[k][tx * 4];
#pragma unroll
            for (int i = 0; i < 4; i++)
#pragma unroll
                for (int j = 0; j < 4; j++)
                    acc[i][j] = fmaf(a[i], bb[j], acc[i][j]);
        }
    }
#pragma unroll
    for (int i = 0; i < 4; i++) {
        int m = m0 + ty * 4 + i;
        float4 o;
        o.x = acc[i][0] + be[n0 + tx * 4 + 0];
        o.y = acc[i][1] + be[n0 + tx * 4 + 1];
        o.z = acc[i][2] + be[n0 + tx * 4 + 2];
        o.w = acc[i][3] + be[n0 + tx * 4 + 3];
        *(float4*)&g_hWe[(size_t)m * Hh_ + n0 + tx * 4] = o;
    }
}

// ---------------------------------------------------------------------------
// S2: scores[b][o] = sum_n w[n] * tanh( (x_j @ Ue^T)[b,o,n] + hWe[b][n] )
//     One CTA = one batch b (BM = O = 128 rows), K=512, N=512 in 4 chunks.
//     BM=128, BN=128, BK=16, 256 thr, 8x8 microtile.
//     DOUBLE-BUFFERED smem: 1 syncthreads per k-tile, loads overlap compute.
// ---------------------------------------------------------------------------
__global__ __launch_bounds__(256, 2) void s2_kernel(const float* __restrict__ xj,
                                                    const float* __restrict__ Ue,
                                                    const float* __restrict__ w) {
    __shared__ __align__(16) float As[2][16][132];
    __shared__ __align__(16) float Bs[2][16][132];
    __shared__ float red[128][17];
    const int tid = threadIdx.x;
    const int tx = tid & 15, ty = tid >> 4;
    const int bidx = blockIdx.x;       // batch index
    const int m0 = bidx * 128;
    const int lrow = tid >> 2;
    const int lc4  = (tid & 3) * 4;

    const float* aptr0 = xj + (size_t)(m0 + lrow)      * Hh_ + lc4;
    const float* aptr1 = xj + (size_t)(m0 + lrow + 64) * Hh_ + lc4;

    float rowsum[8] = {};
    for (int nc = 0; nc < 4; nc++) {
        const int n0 = nc * 128;
        const float* bptr0 = Ue + (size_t)(n0 + lrow)      * Hh_ + lc4;
        const float* bptr1 = Ue + (size_t)(n0 + lrow + 64) * Hh_ + lc4;
        float acc[8][8] = {};

        // preload k-tile 0 into buffer 0
        {
            float4 a0 = *(const float4*)(aptr0);
            float4 a1 = *(const float4*)(aptr1);
            float4 b0 = *(const float4*)(bptr0);
            float4 b1 = *(const float4*)(bptr1);
            As[0][lc4 + 0][lrow] = a0.x; As[0][lc4 + 1][lrow] = a0.y;
            As[0][lc4 + 2][lrow] = a0.z; As[0][lc4 + 3][lrow] = a0.w;
            As[0][lc4 + 0][lrow + 64] = a1.x; As[0][lc4 + 1][lrow + 64] = a1.y;
            As[0][lc4 + 2][lrow + 64] = a1.z; As[0][lc4 + 3][lrow + 64] = a1.w;
            Bs[0][lc4 + 0][lrow] = b0.x; Bs[0][lc4 + 1][lrow] = b0.y;
            Bs[0][lc4 + 2][lrow] = b0.z; Bs[0][lc4 + 3][lrow] = b0.w;
            Bs[0][lc4 + 0][lrow + 64] = b1.x; Bs[0][lc4 + 1][lrow + 64] = b1.y;
            Bs[0][lc4 + 2][lrow + 64] = b1.z; Bs[0][lc4 + 3][lrow + 64] = b1.w;
        }
        __syncthreads();

        const int NT = Hh_ / 16;   // 32 k-tiles
#pragma unroll 2
        for (int kt = 0; kt < NT; kt++) {
            const int cur = kt & 1;
            const bool more = (kt + 1 < NT);
            float4 a0, a1, b0, b1;
            if (more) {
                const int kk = (kt + 1) * 16;
                a0 = *(const float4*)(aptr0 + kk);
                a1 = *(const float4*)(aptr1 + kk);
                b0 = *(const float4*)(bptr0 + kk);
                b1 = *(const float4*)(bptr1 + kk);
            }
#pragma unroll
            for (int k = 0; k < 16; k++) {
                float a[8], bb[8];
                *(float4*)(a)      = *(const float4*)&As[cur][k][ty * 4];
                *(float4*)(a + 4)  = *(const float4*)&As[cur][k][64 + ty * 4];
                *(float4*)(bb)     = *(const float4*)&Bs[cur][k][tx * 4];
                *(float4*)(bb + 4) = *(const float4*)&Bs[cur][k][64 + tx * 4];
#pragma unroll
                for (int i = 0; i < 8; i++)
#pragma unroll
                    for (int j = 0; j < 8; j++)
                        acc[i][j] = fmaf(a[i], bb[j], acc[i][j]);
            }
            if (more) {
                const int nxt = cur ^ 1;
                As[nxt][lc4 + 0][lrow] = a0.x; As[nxt][lc4 + 1][lrow] = a0.y;
                As[nxt][lc4 + 2][lrow] = a0.z; As[nxt][lc4 + 3][lrow] = a0.w;
                As[nxt][lc4 + 0][lrow + 64] = a1.x; As[nxt][lc4 + 1][lrow + 64] = a1.y;
                As[nxt][lc4 + 2][lrow + 64] = a1.z; As[nxt][lc4 + 3][lrow + 64] = a1.w;
                Bs[nxt][lc4 + 0][lrow] = b0.x; Bs[nxt][lc4 + 1][lrow] = b0.y;
                Bs[nxt][lc4 + 2][lrow] = b0.z; Bs[nxt][lc4 + 3][lrow] = b0.w;
                Bs[nxt][lc4 + 0][lrow + 64] = b1.x; Bs[nxt][lc4 + 1][lrow + 64] = b1.y;
                Bs[nxt][lc4 + 2][lrow + 64] = b1.z; Bs[nxt][lc4 + 3][lrow + 64] = b1.w;
                __syncthreads();
            }
        }

        // fused epilogue: tanh + dot with w, accumulated per row
#pragma unroll
        for (int j = 0; j < 8; j++) {
            int n = n0 + ((j < 4) ? (tx * 4 + j) : (64 + tx * 4 + j - 4));
            float hv = g_hWe[(size_t)bidx * Hh_ + n];
            float wv = w[n];
#pragma unroll
            for (int i = 0; i < 8; i++)
                rowsum[i] += wv * tanhf(acc[i][j] + hv);
        }
        // NOTE: next nc preloads into buffer 0; buffer 0's last readers were
        // all released by the sync at the end of k-tile NT-2, so no hazard.
    }

    // reduce rowsum over the 16 thread-columns
#pragma unroll
    for (int i = 0; i < 8; i++) {
        int rl = (i < 4) ? (ty * 4 + i) : (64 + ty * 4 + i - 4);
        red[rl][tx] = rowsum[i];
    }
    __syncthreads();
    if (tid < 128) {
        float s = 0.f;
#pragma unroll
        for (int t = 0; t < 16; t++) s += red[tid][t];
        g_scores[m0 + tid] = s;
    }
}

// ---------------------------------------------------------------------------
// S3: masked softmax over O per batch + phi[b][k] = sum_o a[b][o] * x_j[b][o][k]
//     Mask encoding resolved at runtime by s0: word-read (int32/f32, "!=0")
//     or byte-read (packed bool).
// ---------------------------------------------------------------------------
__global__ __launch_bounds__(256) void s3_kernel(const void* __restrict__ maskv,
                                                 const float* __restrict__ xj) {
    __shared__ float ebuf[128];
    __shared__ float rbuf[128];
    __shared__ float abuf[128];
    const int b = blockIdx.x;
    const int tid = threadIdx.x;

    if (tid < 128) {
        float s = g_scores[b * O_ + tid];
        bool valid;
        if (g_mask_u8)
            valid = ((const unsigned char*)maskv)[b * O_ + tid] != 0;
        else
            valid = ((const int*)maskv)[b * O_ + tid] != 0;
        float e = valid ? s : -1e9f;
        ebuf[tid] = e;
        rbuf[tid] = e;
    }
    __syncthreads();
    for (int st = 64; st >= 1; st >>= 1) {
        if (tid < st) rbuf[tid] = fmaxf(rbuf[tid], rbuf[tid + st]);
        __syncthreads();
    }
    const float mx = rbuf[0];
    __syncthreads();
    if (tid < 128) {
        float p = expf(ebuf[tid] - mx);
        abuf[tid] = p;
        rbuf[tid] = p;
    }
    __syncthreads();
    for (int st = 64; st >= 1; st >>= 1) {
        if (tid < st) rbuf[tid] += rbuf[tid + st];
        __syncthreads();
    }
    const float inv = 1.f / rbuf[0];
    __syncthreads();
    if (tid < 128) abuf[tid] *= inv;
    __syncthreads();

    const float* xb = xj + (size_t)b * O_ * Hh_;
    for (int k = tid; k < Hh_; k += 256) {
        float s = 0.f;
#pragma unroll 4
        for (int o = 0; o < O_; o++)
            s = fmaf(abuf[o], xb[(size_t)o * Hh_ + k], s);
        g_phi[(size_t)b * Hh_ + k] = s;
    }
}

// ---------------------------------------------------------------------------
// S4 helpers: segmented A/B tile loads for the concatenated K dimension.
// ---------------------------------------------------------------------------
__device__ __forceinline__ void s4_load_tiles(
    int kg, int m0, int n0, int lrow, int lc4, int g,
    const float* __restrict__ XF, const float* __restrict__ hh,
    const float* __restrict__ cc, const GatePtrs& P,
    const float* __restrict__ phi,
    float4& a0, float4& a1, float4& b0, float4& b1)
{
    // A source segment
    const float* ap; int astr, ac;
    if (kg < 512)       { ap = phi; astr = Hh_; ac = kg;        }
    else if (kg < 2048) { ap = XF;  astr = DF_; ac = kg - 512;  }
    else if (kg < 3072) { ap = hh;  astr = H_;  ac = kg - 2048; }
    else                { ap = cc;  astr = H_;  ac = kg - 3072; }
    a0 = *(const float4*)(ap + (size_t)(m0 + lrow)      * astr + ac + lc4);
    a1 = *(const float4*)(ap + (size_t)(m0 + lrow + 64) * astr + ac + lc4);
    // B (weight) segment
    const float* bp; int bstr, bc;
    if (kg < 2048)      { bp = P.W[g]; bstr = I_; bc = kg;        }
    else if (kg < 3072) { bp = P.U[g]; bstr = H_; bc = kg - 2048; }
    else                { bp = (g == 2) ? (const float*)0 : P.V[g]; bstr = H_; bc = kg - 3072; }
    if (bp) {
        b0 = *(const float4*)(bp + (size_t)(n0 + lrow)      * bstr + bc + lc4);
        b1 = *(const float4*)(bp + (size_t)(n0 + lrow + 64) * bstr + bc + lc4);
    } else {
        b0 = make_float4(0.f, 0.f, 0.f, 0.f); b1 = b0;
    }
}

// ---------------------------------------------------------------------------
// S4: gate pre-activations, split-K, DOUBLE-BUFFERED smem.
//     A row (K=4096) = [phi(512) | X_F(1536) | h(1024) | c(1024)]
//     B row (gate g) = [W_g(2048) | U_g(1024) | V_g(1024, zero for gate c)]
//     M=256, N=1024, grid (2 m-tiles, 8 n-tiles, 16 = 4 gates x 4 k-splits).
// ---------------------------------------------------------------------------
__global__ __launch_bounds__(256, 2) void s4_kernel(const float* __restrict__ XF,
                                                    const float* __restrict__ hh,
                                                    const float* __restrict__ cc,
                                                    GatePtrs P) {
    __shared__ __align__(16) float As[2][16][132];
    __shared__ __align__(16) float Bs[2][16][132];
    const int tid = threadIdx.x;
    const int tx = tid & 15, ty = tid >> 4;
    const int m0 = blockIdx.x * 128;
    const int n0 = blockIdx.y * 128;
    const int g  = blockIdx.z & 3;
    const int ks = blockIdx.z >> 2;
    const int lrow = tid >> 2;
    const int lc4  = (tid & 3) * 4;
    const int kbase = ks * 1024;

    float acc[8][8] = {};

    // preload k-tile 0 into buffer 0
    {
        float4 a0, a1, b0, b1;
        s4_load_tiles(kbase, m0, n0, lrow, lc4, g, XF, hh, cc, P, g_phi, a0, a1, b0, b1);
        As[0][lc4 + 0][lrow] = a0.x; As[0][lc4 + 1][lrow] = a0.y;
        As[0][lc4 + 2][lrow] = a0.z; As[0][lc4 + 3][lrow] = a0.w;
        As[0][lc4 + 0][lrow + 64] = a1.x; As[0][lc4 + 1][lrow + 64] = a1.y;
        As[0][lc4 + 2][lrow + 64] = a1.z; As[0][lc4 + 3][lrow + 64] = a1.w;
        Bs[0][lc4 + 0][lrow] = b0.x; Bs[0][lc4 + 1][lrow] = b0.y;
        Bs[0][lc4 + 2][lrow] = b0.z; Bs[0][lc4 + 3][lrow] = b0.w;
        Bs[0][lc4 + 0][lrow + 64] = b1.x; Bs[0][lc4 + 1][lrow + 64] = b1.y;
        Bs[0][lc4 + 2][lrow + 64] = b1.z; Bs[0][lc4 + 3][lrow + 64] = b1.w;
    }
    __syncthreads();

    const int NT = 1024 / 16;   // 64 k-tiles
#pragma unroll 2
    for (int kt = 0; kt < NT; kt++) {
        const int cur = kt & 1;
        const bool more = (kt + 1 < NT);
        float4 a0, a1, b0, b1;
        if (more)
            s4_load_tiles(kbase + (kt + 1) * 16, m0, n0, lrow, lc4, g,
                          XF, hh, cc, P, g_phi, a0, a1, b0, b1);
#pragma unroll
        for (int k = 0; k < 16; k++) {
            float a[8], bb[8];
            *(float4*)(a)      = *(const float4*)&As[cur][k][ty * 4];
            *(float4*)(a + 4)  = *(const float4*)&As[cur][k][64 + ty * 4];
            *(float4*)(bb)     = *(const float4*)&Bs[cur][k][tx * 4];
            *(float4*)(bb + 4) = *(const float4*)&Bs[cur][k][64 + tx * 4];
#pragma unroll
            for (int i = 0; i < 8; i++)
#pragma unroll
                for (int j = 0; j < 8; j++)
                    acc[i][j] = fmaf(a[i], bb[j], acc[i][j]);
        }
        if (more) {
            const int nxt = cur ^ 1;
            As[nxt][lc4 + 0][lrow] = a0.x; As[nxt][lc4 + 1][lrow] = a0.y;
            As[nxt][lc4 + 2][lrow] = a0.z; As[nxt][lc4 + 3][lrow] = a0.w;
            As[nxt][lc4 + 0][lrow + 64] = a1.x; As[nxt][lc4 + 1][lrow + 64] = a1.y;
            As[nxt][lc4 + 2][lrow + 64] = a1.z; As[nxt][lc4 + 3][lrow + 64] = a1.w;
            Bs[nxt][lc4 + 0][lrow] = b0.x; Bs[nxt][lc4 + 1][lrow] = b0.y;
            Bs[nxt][lc4 + 2][lrow] = b0.z; Bs[nxt][lc4 + 3][lrow] = b0.w;
            Bs[nxt][lc4 + 0][lrow + 64] = b1.x; Bs[nxt][lc4 + 1][lrow + 64] = b1.y;
            Bs[nxt][lc4 + 2][lrow + 64] = b1.z; Bs[nxt][lc4 + 3][lrow + 64] = b1.w;
            __syncthreads();
        }
    }

    const size_t base = (size_t)(ks * 4 + g) * B_ * H_;
#pragma unroll
    for (int i = 0; i < 8; i++) {
        int m = m0 + ((i < 4) ? (ty * 4 + i) : (64 + ty * 4 + i - 4));
        float4 v0 = make_float4(acc[i][0], acc[i][1], acc[i][2], acc[i][3]);
        float4 v1 = make_float4(acc[i][4], acc[i][5], acc[i][6], acc[i][7]);
        *(float4*)&g_part[base + (size_t)m * H_ + n0 + tx * 4]      = v0;
        *(float4*)&g_part[base + (size_t)m * H_ + n0 + 64 + tx * 4] = v1;
    }
}

// ---------------------------------------------------------------------------
// S5: reduce k-splits + bias, gate nonlinearities, LSTM combine.
//     out = [new_h (256x1024) | new_c (256x1024)]
// ---------------------------------------------------------------------------
__global__ __launch_bounds__(256) void s5_kernel(const float* __restrict__ cc,
                                                 BiasPtrs BP,
                                                 float* __restrict__ out) {
    const int idx = blockIdx.x * 256 + threadIdx.x;   // 0 .. 262143
    const int n = idx & (H_ - 1);
    float pre[4];
#pragma unroll
    for (int g = 0; g < 4; g++) {
        float s = BP.b[g][n];
#pragma unroll
        for (int ksp = 0; ksp < 4; ksp++)
            s += g_part[(size_t)(ksp * 4 + g) * B_ * H_ + idx];
        pre[g] = s;
    }
    float iv = 1.f / (1.f + expf(-pre[0]));
    float fv = 1.f / (1.f + expf(-pre[1]));
    float gv = tanhf(pre[2]);
    float ov = 1.f / (1.f + expf(-pre[3]));
    float cold = cc[idx];
    float ncv = fv * cold + iv * gv;
    float nhv = ov * tanhf(ncv);
    out[idx] = nhv;
    out[B_ * H_ + idx] = ncv;
}

// ---------------------------------------------------------------------------
extern "C" void kernel_launch(void* const* d_in, const int* in_sizes, int n_in,
                              void* d_out, int out_size) {
    const float* x_j    = (const float*)d_in[0];
    const void*  x_mask = d_in[1];
    const float* X_F    = (const float*)d_in[2];
    const float* h      = (const float*)d_in[3];
    const float* c      = (const float*)d_in[4];

    GatePtrs P;
    BiasPtrs BP;
    for (int g = 0; g < 4; g++) {
        P.W[g]  = (const float*)d_in[5 + g];
        P.U[g]  = (const float*)d_in[9 + g];
        P.V[g]  = (const float*)d_in[13 + g];
        BP.b[g] = (const float*)d_in[17 + g];
    }
    const float* w  = (const float*)d_in[21];
    const float* We = (const float*)d_in[22];
    const float* Ue = (const float*)d_in[23];
    const float* be = (const float*)d_in[24];
    float* out = (float*)d_out;

    s0_detect_kernel<<<1, 256>>>((const unsigned int*)x_mask);
    s1_kernel<<<dim3(4, 8), 256>>>(h, We, be);
    s2_kernel<<<256, 256>>>(x_j, Ue, w);
    s3_kernel<<<256, 256>>>(x_mask, x_j);
    s4_kernel<<<dim3(2, 8, 16), 256>>>(X_F, h, c, P);
    s5_kernel<<<1024, 256>>>(c, BP, out);
}

// round 12
// speedup vs baseline: 1.8053x; 1.8053x over previous
#include <cuda_runtime.h>
#include <math.h>
#include <stdint.h>

// Problem dims
#define B_   256
#define O_   128
#define H_   1024
#define Hh_  512
#define I_   2048
#define DF_  1536

// Scratch (static device memory: allocation-free, graph-capturable)
__device__ int   g_mask_u8;                  // S0 out: 1 if mask is byte-packed bool
__device__ float g_hWe[B_ * Hh_];            // S1 out: h@We^T + b_e   (256x512)
__device__ float g_scores[B_ * O_];          // S2 out: attention logits (256x128)
__device__ float g_phi[B_ * Hh_];            // S3 out: attended x_j    (256x512)
__device__ float g_part[4 * 4 * B_ * H_];    // S4 out: [ksplit][gate][b][n] partials

struct GatePtrs { const float* W[4]; const float* U[4]; const float* V[4]; };
struct BiasPtrs { const float* b[4]; };

// ---------------------------------------------------------------------------
// tf32 helpers
// ---------------------------------------------------------------------------
__device__ __forceinline__ float tf32_rna(float x) {
    float y;
    asm("cvt.rna.tf32.f32 %0, %1;" : "=f"(y) : "f"(x));
    return y;
}

__device__ __forceinline__ void mma_tf32(float& d0, float& d1, float& d2, float& d3,
                                         uint32_t a0, uint32_t a1, uint32_t a2, uint32_t a3,
                                         uint32_t b0, uint32_t b1) {
    asm volatile(
        "mma.sync.aligned.m16n8k8.row.col.f32.tf32.tf32.f32 "
        "{%0,%1,%2,%3}, {%4,%5,%6,%7}, {%8,%9}, {%0,%1,%2,%3};\n"
        : "+f"(d0), "+f"(d1), "+f"(d2), "+f"(d3)
        : "r"(a0), "r"(a1), "r"(a2), "r"(a3), "r"(b0), "r"(b1));
}

// smem tile stride: 136 floats => k*136 mod 32 = 8k, so the 4 k-rows of a
// fragment land in disjoint bank groups {0-7,8-15,16-23,24-31}: frag loads
// are conflict-free (stores are 4-way conflicted; loads dominate 3:1).
#define TS 136

// ---------------------------------------------------------------------------
// S0: detect mask encoding (validated R8). Reads first B*O/4 words (32 KB).
// ---------------------------------------------------------------------------
__global__ void s0_detect_kernel(const unsigned int* __restrict__ mw) {
    __shared__ int bad;
    if (threadIdx.x == 0) bad = 0;
    __syncthreads();
    int mybad = 0;
    for (int i = threadIdx.x; i < (B_ * O_) / 4; i += blockDim.x) {
        unsigned int v = mw[i];
        if (v != 0u && v != 1u && v != 0x3F800000u) mybad = 1;
    }
    if (mybad) bad = 1;           // benign race: only ever writes 1
    __syncthreads();
    if (threadIdx.x == 0) g_mask_u8 = bad;
}

// ---------------------------------------------------------------------------
// S1: g_hWe[b][n] = b_e[n] + sum_j h[b][j]*W_e[n][j]. (validated; fp32 SIMT)
// ---------------------------------------------------------------------------
__global__ __launch_bounds__(256) void s1_kernel(const float* __restrict__ h,
                                                 const float* __restrict__ We,
                                                 const float* __restrict__ be) {
    __shared__ __align__(16) float As[16][68];
    __shared__ __align__(16) float Bs[16][68];
    const int tid = threadIdx.x;
    const int tx = tid & 15, ty = tid >> 4;
    const int m0 = blockIdx.x * 64, n0 = blockIdx.y * 64;
    const int lrow = tid >> 2;
    const int lc4  = (tid & 3) * 4;

    float acc[4][4] = {};
    for (int k0 = 0; k0 < H_; k0 += 16) {
        float4 av = *(const float4*)(h  + (size_t)(m0 + lrow) * H_ + k0 + lc4);
        float4 bv = *(const float4*)(We + (size_t)(n0 + lrow) * H_ + k0 + lc4);
        __syncthreads();
        As[lc4 + 0][lrow] = av.x; As[lc4 + 1][lrow] = av.y;
        As[lc4 + 2][lrow] = av.z; As[lc4 + 3][lrow] = av.w;
        Bs[lc4 + 0][lrow] = bv.x; Bs[lc4 + 1][lrow] = bv.y;
        Bs[lc4 + 2][lrow] = bv.z; Bs[lc4 + 3][lrow] = bv.w;
        __syncthreads();
#pragma unroll
        for (int k = 0; k < 16; k++) {
            float a[4], bb[4];
            *(float4*)a  = *(const float4*)&As[k][ty * 4];
            *(float4*)bb = *(const float4*)&Bs[k][tx * 4];
#pragma unroll
            for (int i = 0; i < 4; i++)
#pragma unroll
                for (int j = 0; j < 4; j++)
                    acc[i][j] = fmaf(a[i], bb[j], acc[i][j]);
        }
    }
#pragma unroll
    for (int i = 0; i < 4; i++) {
        int m = m0 + ty * 4 + i;
        float4 o;
        o.x = acc[i][0] + be[n0 + tx * 4 + 0];
        o.y = acc[i][1] + be[n0 + tx * 4 + 1];
        o.z = acc[i][2] + be[n0 + tx * 4 + 2];
        o.w = acc[i][3] + be[n0 + tx * 4 + 3];
        *(float4*)&g_hWe[(size_t)m * Hh_ + n0 + tx * 4] = o;
    }
}

// ---------------------------------------------------------------------------
// S2 (TENSOR): scores[b][o] = sum_n w[n]*tanh((x_j@Ue^T)[b,o,n] + hWe[b][n])
//     One CTA per batch. BM=128 (=O), BN=128 (4 chunks over N=512), BK=16.
//     mma.sync m16n8k8 tf32, warp grid 4(m)x2(n), warp tile 32x64.
//     Double-buffered smem, tf32-rounded at smem store, fp32 accumulate.
// ---------------------------------------------------------------------------
__global__ __launch_bounds__(256, 2) void s2_kernel(const float* __restrict__ xj,
                                                    const float* __restrict__ Ue,
                                                    const float* __restrict__ w) {
    __shared__ float As[2][16][TS];
    __shared__ float Bs[2][16][TS];
    __shared__ float hWs[512], ws[512];
    __shared__ float red[128][2];
    const int tid  = threadIdx.x;
    const int lane = tid & 31, wid = tid >> 5;
    const int wm = wid & 3, wn = wid >> 2;       // warp grid 4 x 2
    const int mw = wm * 32, nw = wn * 64;
    const int lk = lane & 3, lm = lane >> 2;
    const int bidx = blockIdx.x;
    const int m0 = bidx * 128;
    const int lrow = tid >> 2;                   // 0..63
    const int lc4  = (tid & 3) * 4;

    for (int i = tid; i < 512; i += 256) { hWs[i] = g_hWe[(size_t)bidx * Hh_ + i]; ws[i] = w[i]; }

    const float* aptr0 = xj + (size_t)(m0 + lrow)      * Hh_ + lc4;
    const float* aptr1 = xj + (size_t)(m0 + lrow + 64) * Hh_ + lc4;

    float rowsum[4] = {};
    for (int nc = 0; nc < 4; nc++) {
        const int n0 = nc * 128;
        const float* bptr0 = Ue + (size_t)(n0 + lrow)      * Hh_ + lc4;
        const float* bptr1 = Ue + (size_t)(n0 + lrow + 64) * Hh_ + lc4;
        float acc[2][8][4] = {};

        // preload k-tile 0 into buffer 0 (tf32-rounded)
        {
            float4 a0 = *(const float4*)(aptr0);
            float4 a1 = *(const float4*)(aptr1);
            float4 b0 = *(const float4*)(bptr0);
            float4 b1 = *(const float4*)(bptr1);
            As[0][lc4 + 0][lrow] = tf32_rna(a0.x); As[0][lc4 + 1][lrow] = tf32_rna(a0.y);
            As[0][lc4 + 2][lrow] = tf32_rna(a0.z); As[0][lc4 + 3][lrow] = tf32_rna(a0.w);
            As[0][lc4 + 0][lrow + 64] = tf32_rna(a1.x); As[0][lc4 + 1][lrow + 64] = tf32_rna(a1.y);
            As[0][lc4 + 2][lrow + 64] = tf32_rna(a1.z); As[0][lc4 + 3][lrow + 64] = tf32_rna(a1.w);
            Bs[0][lc4 + 0][lrow] = tf32_rna(b0.x); Bs[0][lc4 + 1][lrow] = tf32_rna(b0.y);
            Bs[0][lc4 + 2][lrow] = tf32_rna(b0.z); Bs[0][lc4 + 3][lrow] = tf32_rna(b0.w);
            Bs[0][lc4 + 0][lrow + 64] = tf32_rna(b1.x); Bs[0][lc4 + 1][lrow + 64] = tf32_rna(b1.y);
            Bs[0][lc4 + 2][lrow + 64] = tf32_rna(b1.z); Bs[0][lc4 + 3][lrow + 64] = tf32_rna(b1.w);
        }
        __syncthreads();

        const int NT = Hh_ / 16;   // 32 k-tiles
        for (int kt = 0; kt < NT; kt++) {
            const int cur = kt & 1;
            const bool more = (kt + 1 < NT);
            float4 a0, a1, b0, b1;
            if (more) {
                const int kk = (kt + 1) * 16;
                a0 = *(const float4*)(aptr0 + kk);
                a1 = *(const float4*)(aptr1 + kk);
                b0 = *(const float4*)(bptr0 + kk);
                b1 = *(const float4*)(bptr1 + kk);
            }
#pragma unroll
            for (int ks = 0; ks < 16; ks += 8) {
                uint32_t af[2][4];
#pragma unroll
                for (int mt = 0; mt < 2; mt++) {
                    af[mt][0] = __float_as_uint(As[cur][ks + lk    ][mw + mt * 16 + lm    ]);
                    af[mt][1] = __float_as_uint(As[cur][ks + lk    ][mw + mt * 16 + lm + 8]);
                    af[mt][2] = __float_as_uint(As[cur][ks + lk + 4][mw + mt * 16 + lm    ]);
                    af[mt][3] = __float_as_uint(As[cur][ks + lk + 4][mw + mt * 16 + lm + 8]);
                }
#pragma unroll
                for (int nt = 0; nt < 8; nt++) {
                    uint32_t bf0 = __float_as_uint(Bs[cur][ks + lk    ][nw + nt * 8 + lm]);
                    uint32_t bf1 = __float_as_uint(Bs[cur][ks + lk + 4][nw + nt * 8 + lm]);
                    mma_tf32(acc[0][nt][0], acc[0][nt][1], acc[0][nt][2], acc[0][nt][3],
                             af[0][0], af[0][1], af[0][2], af[0][3], bf0, bf1);
                    mma_tf32(acc[1][nt][0], acc[1][nt][1], acc[1][nt][2], acc[1][nt][3],
                             af[1][0], af[1][1], af[1][2], af[1][3], bf0, bf1);
                }
            }
            if (more) {
                const int nxt = cur ^ 1;
                As[nxt][lc4 + 0][lrow] = tf32_rna(a0.x); As[nxt][lc4 + 1][lrow] = tf32_rna(a0.y);
                As[nxt][lc4 + 2][lrow] = tf32_rna(a0.z); As[nxt][lc4 + 3][lrow] = tf32_rna(a0.w);
                As[nxt][lc4 + 0][lrow + 64] = tf32_rna(a1.x); As[nxt][lc4 + 1][lrow + 64] = tf32_rna(a1.y);
                As[nxt][lc4 + 2][lrow + 64] = tf32_rna(a1.z); As[nxt][lc4 + 3][lrow + 64] = tf32_rna(a1.w);
                Bs[nxt][lc4 + 0][lrow] = tf32_rna(b0.x); Bs[nxt][lc4 + 1][lrow] = tf32_rna(b0.y);
                Bs[nxt][lc4 + 2][lrow] = tf32_rna(b0.z); Bs[nxt][lc4 + 3][lrow] = tf32_rna(b0.w);
                Bs[nxt][lc4 + 0][lrow + 64] = tf32_rna(b1.x); Bs[nxt][lc4 + 1][lrow + 64] = tf32_rna(b1.y);
                Bs[nxt][lc4 + 2][lrow + 64] = tf32_rna(b1.z); Bs[nxt][lc4 + 3][lrow + 64] = tf32_rna(b1.w);
                __syncthreads();
            }
        }

        // fused epilogue: tanh + dot with w, accumulated per thread-row
#pragma unroll
        for (int mt = 0; mt < 2; mt++)
#pragma unroll
        for (int r = 0; r < 2; r++) {
            float s = 0.f;
#pragma unroll
            for (int nt = 0; nt < 8; nt++)
#pragma unroll
            for (int c = 0; c < 2; c++) {
                int n = n0 + nw + nt * 8 + (lane & 3) * 2 + c;
                s += ws[n] * tanhf(acc[mt][nt][r * 2 + c] + hWs[n]);
            }
            rowsum[mt * 2 + r] += s;
        }
        // buffer-0 reuse across nc is safe: its last readers were released by
        // the syncthreads at the end of k-tile NT-2.
    }

    // quad reduce (lanes sharing lane>>2 hold the same rows, different cols)
#pragma unroll
    for (int i = 0; i < 4; i++) {
        float v = rowsum[i];
        v += __shfl_xor_sync(0xffffffffu, v, 1);
        v += __shfl_xor_sync(0xffffffffu, v, 2);
        if ((lane & 3) == 0) {
            int mt = i >> 1, r = i & 1;
            int row = mw + mt * 16 + r * 8 + lm;
            red[row][wn] = v;
        }
    }
    __syncthreads();
    if (tid < 128) g_scores[m0 + tid] = red[tid][0] + red[tid][1];
}

// ---------------------------------------------------------------------------
// S3: masked softmax + phi. Grid 1024: 4 k-slices per batch, softmax
//     recomputed per slice (bit-identical). Mask encoding via s0 flag.
// ---------------------------------------------------------------------------
__global__ __launch_bounds__(128) void s3_kernel(const void* __restrict__ maskv,
                                                 const float* __restrict__ xj) {
    __shared__ float ebuf[128];
    __shared__ float rbuf[128];
    __shared__ float abuf[128];
    const int b     = blockIdx.x >> 2;
    const int slice = blockIdx.x & 3;
    const int tid = threadIdx.x;

    float s0 = g_scores[b * O_ + tid];
    bool valid;
    if (g_mask_u8)
        valid = ((const unsigned char*)maskv)[b * O_ + tid] != 0;
    else
        valid = ((const int*)maskv)[b * O_ + tid] != 0;
    float e = valid ? s0 : -1e9f;
    ebuf[tid] = e;
    rbuf[tid] = e;
    __syncthreads();
    for (int st = 64; st >= 1; st >>= 1) {
        if (tid < st) rbuf[tid] = fmaxf(rbuf[tid], rbuf[tid + st]);
        __syncthreads();
    }
    const float mx = rbuf[0];
    __syncthreads();
    float p = expf(ebuf[tid] - mx);
    abuf[tid] = p;
    rbuf[tid] = p;
    __syncthreads();
    for (int st = 64; st >= 1; st >>= 1) {
        if (tid < st) rbuf[tid] += rbuf[tid + st];
        __syncthreads();
    }
    const float inv = 1.f / rbuf[0];
    __syncthreads();
    abuf[tid] *= inv;
    __syncthreads();

    const float* xb = xj + (size_t)b * O_ * Hh_;
    const int k = slice * 128 + tid;
    float acc = 0.f;
#pragma unroll 4
    for (int o = 0; o < O_; o++)
        acc = fmaf(abuf[o], xb[(size_t)o * Hh_ + k], acc);
    g_phi[(size_t)b * Hh_ + k] = acc;
}

// ---------------------------------------------------------------------------
// S4 helper: segmented A/B tile loads for the concatenated K dimension.
// ---------------------------------------------------------------------------
__device__ __forceinline__ void s4_load_tiles(
    int kg, int m0, int n0, int lrow, int lc4, int g,
    const float* __restrict__ XF, const float* __restrict__ hh,
    const float* __restrict__ cc, const GatePtrs& P,
    const float* __restrict__ phi,
    float4& a0, float4& a1, float4& b0, float4& b1)
{
    const float* ap; int astr, ac;
    if (kg < 512)       { ap = phi; astr = Hh_; ac = kg;        }
    else if (kg < 2048) { ap = XF;  astr = DF_; ac = kg - 512;  }
    else if (kg < 3072) { ap = hh;  astr = H_;  ac = kg - 2048; }
    else                { ap = cc;  astr = H_;  ac = kg - 3072; }
    a0 = *(const float4*)(ap + (size_t)(m0 + lrow)      * astr + ac + lc4);
    a1 = *(const float4*)(ap + (size_t)(m0 + lrow + 64) * astr + ac + lc4);
    const float* bp; int bstr, bc;
    if (kg < 2048)      { bp = P.W[g]; bstr = I_; bc = kg;        }
    else if (kg < 3072) { bp = P.U[g]; bstr = H_; bc = kg - 2048; }
    else                { bp = (g == 2) ? (const float*)0 : P.V[g]; bstr = H_; bc = kg - 3072; }
    if (bp) {
        b0 = *(const float4*)(bp + (size_t)(n0 + lrow)      * bstr + bc + lc4);
        b1 = *(const float4*)(bp + (size_t)(n0 + lrow + 64) * bstr + bc + lc4);
    } else {
        b0 = make_float4(0.f, 0.f, 0.f, 0.f); b1 = b0;
    }
}

// ---------------------------------------------------------------------------
// S4 (TENSOR): gate pre-activations, split-K, mma.sync tf32.
//     grid (2 m-tiles, 8 n-tiles, 16 = 4 gates x 4 k-splits), BK=16, K=1024/CTA.
// ---------------------------------------------------------------------------
__global__ __launch_bounds__(256, 2) void s4_kernel(const float* __restrict__ XF,
                                                    const float* __restrict__ hh,
                                                    const float* __restrict__ cc,
                                                    GatePtrs P) {
    __shared__ float As[2][16][TS];
    __shared__ float Bs[2][16][TS];
    const int tid  = threadIdx.x;
    const int lane = tid & 31, wid = tid >> 5;
    const int wm = wid & 3, wn = wid >> 2;
    const int mw = wm * 32, nw = wn * 64;
    const int lk = lane & 3, lm = lane >> 2;
    const int m0 = blockIdx.x * 128;
    const int n0 = blockIdx.y * 128;
    const int g  = blockIdx.z & 3;
    const int ks = blockIdx.z >> 2;
    const int lrow = tid >> 2;
    const int lc4  = (tid & 3) * 4;
    const int kbase = ks * 1024;

    float acc[2][8][4] = {};

    {
        float4 a0, a1, b0, b1;
        s4_load_tiles(kbase, m0, n0, lrow, lc4, g, XF, hh, cc, P, g_phi, a0, a1, b0, b1);
        As[0][lc4 + 0][lrow] = tf32_rna(a0.x); As[0][lc4 + 1][lrow] = tf32_rna(a0.y);
        As[0][lc4 + 2][lrow] = tf32_rna(a0.z); As[0][lc4 + 3][lrow] = tf32_rna(a0.w);
        As[0][lc4 + 0][lrow + 64] = tf32_rna(a1.x); As[0][lc4 + 1][lrow + 64] = tf32_rna(a1.y);
        As[0][lc4 + 2][lrow + 64] = tf32_rna(a1.z); As[0][lc4 + 3][lrow + 64] = tf32_rna(a1.w);
        Bs[0][lc4 + 0][lrow] = tf32_rna(b0.x); Bs[0][lc4 + 1][lrow] = tf32_rna(b0.y);
        Bs[0][lc4 + 2][lrow] = tf32_rna(b0.z); Bs[0][lc4 + 3][lrow] = tf32_rna(b0.w);
        Bs[0][lc4 + 0][lrow + 64] = tf32_rna(b1.x); Bs[0][lc4 + 1][lrow + 64] = tf32_rna(b1.y);
        Bs[0][lc4 + 2][lrow + 64] = tf32_rna(b1.z); Bs[0][lc4 + 3][lrow + 64] = tf32_rna(b1.w);
    }
    __syncthreads();

    const int NT = 1024 / 16;   // 64 k-tiles
    for (int kt = 0; kt < NT; kt++) {
        const int cur = kt & 1;
        const bool more = (kt + 1 < NT);
        float4 a0, a1, b0, b1;
        if (more)
            s4_load_tiles(kbase + (kt + 1) * 16, m0, n0, lrow, lc4, g,
                          XF, hh, cc, P, g_phi, a0, a1, b0, b1);
#pragma unroll
        for (int kss = 0; kss < 16; kss += 8) {
            uint32_t af[2][4];
#pragma unroll
            for (int mt = 0; mt < 2; mt++) {
                af[mt][0] = __float_as_uint(As[cur][kss + lk    ][mw + mt * 16 + lm    ]);
                af[mt][1] = __float_as_uint(As[cur][kss + lk    ][mw + mt * 16 + lm + 8]);
                af[mt][2] = __float_as_uint(As[cur][kss + lk + 4][mw + mt * 16 + lm    ]);
                af[mt][3] = __float_as_uint(As[cur][kss + lk + 4][mw + mt * 16 + lm + 8]);
            }
#pragma unroll
            for (int nt = 0; nt < 8; nt++) {
                uint32_t bf0 = __float_as_uint(Bs[cur][kss + lk    ][nw + nt * 8 + lm]);
                uint32_t bf1 = __float_as_uint(Bs[cur][kss + lk + 4][nw + nt * 8 + lm]);
                mma_tf32(acc[0][nt][0], acc[0][nt][1], acc[0][nt][2], acc[0][nt][3],
                         af[0][0], af[0][1], af[0][2], af[0][3], bf0, bf1);
                mma_tf32(acc[1][nt][0], acc[1][nt][1], acc[1][nt][2], acc[1][nt][3],
                         af[1][0], af[1][1], af[1][2], af[1][3], bf0, bf1);
            }
        }
        if (more) {
            const int nxt = cur ^ 1;
            As[nxt][lc4 + 0][lrow] = tf32_rna(a0.x); As[nxt][lc4 + 1][lrow] = tf32_rna(a0.y);
            As[nxt][lc4 + 2][lrow] = tf32_rna(a0.z); As[nxt][lc4 + 3][lrow] = tf32_rna(a0.w);
            As[nxt][lc4 + 0][lrow + 64] = tf32_rna(a1.x); As[nxt][lc4 + 1][lrow + 64] = tf32_rna(a1.y);
            As[nxt][lc4 + 2][lrow + 64] = tf32_rna(a1.z); As[nxt][lc4 + 3][lrow + 64] = tf32_rna(a1.w);
            Bs[nxt][lc4 + 0][lrow] = tf32_rna(b0.x); Bs[nxt][lc4 + 1][lrow] = tf32_rna(b0.y);
            Bs[nxt][lc4 + 2][lrow] = tf32_rna(b0.z); Bs[nxt][lc4 + 3][lrow] = tf32_rna(b0.w);
            Bs[nxt][lc4 + 0][lrow + 64] = tf32_rna(b1.x); Bs[nxt][lc4 + 1][lrow + 64] = tf32_rna(b1.y);
            Bs[nxt][lc4 + 2][lrow + 64] = tf32_rna(b1.z); Bs[nxt][lc4 + 3][lrow + 64] = tf32_rna(b1.w);
            __syncthreads();
        }
    }

    const size_t base = (size_t)(ks * 4 + g) * B_ * H_;
#pragma unroll
    for (int mt = 0; mt < 2; mt++)
#pragma unroll
    for (int nt = 0; nt < 8; nt++)
#pragma unroll
    for (int r = 0; r < 2; r++) {
        int m = m0 + mw + mt * 16 + r * 8 + lm;
        int n = n0 + nw + nt * 8 + (lane & 3) * 2;
        float2 v = make_float2(acc[mt][nt][r * 2 + 0], acc[mt][nt][r * 2 + 1]);
        *(float2*)&g_part[base + (size_t)m * H_ + n] = v;
    }
}

// ---------------------------------------------------------------------------
// S5: reduce k-splits + bias, gate nonlinearities, LSTM combine.
// ---------------------------------------------------------------------------
__global__ __launch_bounds__(256) void s5_kernel(const float* __restrict__ cc,
                                                 BiasPtrs BP,
                                                 float* __restrict__ out) {
    const int idx = blockIdx.x * 256 + threadIdx.x;   // 0 .. 262143
    const int n = idx & (H_ - 1);
    float pre[4];
#pragma unroll
    for (int g = 0; g < 4; g++) {
        float s = BP.b[g][n];
#pragma unroll
        for (int ksp = 0; ksp < 4; ksp++)
            s += g_part[(size_t)(ksp * 4 + g) * B_ * H_ + idx];
        pre[g] = s;
    }
    float iv = 1.f / (1.f + expf(-pre[0]));
    float fv = 1.f / (1.f + expf(-pre[1]));
    float gv = tanhf(pre[2]);
    float ov = 1.f / (1.f + expf(-pre[3]));
    float cold = cc[idx];
    float ncv = fv * cold + iv * gv;
    float nhv = ov * tanhf(ncv);
    out[idx] = nhv;
    out[B_ * H_ + idx] = ncv;
}

// ---------------------------------------------------------------------------
extern "C" void kernel_launch(void* const* d_in, const int* in_sizes, int n_in,
                              void* d_out, int out_size) {
    const float* x_j    = (const float*)d_in[0];
    const void*  x_mask = d_in[1];
    const float* X_F    = (const float*)d_in[2];
    const float* h      = (const float*)d_in[3];
    const float* c      = (const float*)d_in[4];

    GatePtrs P;
    BiasPtrs BP;
    for (int g = 0; g < 4; g++) {
        P.W[g]  = (const float*)d_in[5 + g];
        P.U[g]  = (const float*)d_in[9 + g];
        P.V[g]  = (const float*)d_in[13 + g];
        BP.b[g] = (const float*)d_in[17 + g];
    }
    const float* w  = (const float*)d_in[21];
    const float* We = (const float*)d_in[22];
    const float* Ue = (const float*)d_in[23];
    const float* be = (const float*)d_in[24];
    float* out = (float*)d_out;

    s0_detect_kernel<<<1, 256>>>((const unsigned int*)x_mask);
    s1_kernel<<<dim3(4, 8), 256>>>(h, We, be);
    s2_kernel<<<256, 256>>>(x_j, Ue, w);
    s3_kernel<<<1024, 128>>>(x_mask, x_j);
    s4_kernel<<<dim3(2, 8, 16), 256>>>(X_F, h, c, P);
    s5_kernel<<<1024, 256>>>(c, BP, out);
}